// round 1
// baseline (speedup 1.0000x reference)
#include <cuda_runtime.h>
#include <cuda_bf16.h>
#include <math.h>

typedef unsigned long long ull;

// ---------------- scratch (static device globals; no allocation) ----------------
// g_pre[dir][t][b][c] : pre-activations (x@Wx + bias), 2*512*32*512 floats = 64MB
// g_hs [t][b][j]      : hidden states, j = dir*512 + c, 512*32*1024 floats = 64MB
__device__ float g_pre[2u * 512u * 32u * 512u];
__device__ float g_hs[512u * 32u * 1024u];
__device__ unsigned int g_bar;

// ---------------- f32x2 helpers (packed dual-FMA: 2x fp32 rate on sm_103a) ------
__device__ __forceinline__ ull ffma2(ull a, ull b, ull c) {
    ull d;
    asm("fma.rn.f32x2 %0, %1, %2, %3;" : "=l"(d) : "l"(a), "l"(b), "l"(c));
    return d;
}
__device__ __forceinline__ ull pack2(float x) {
    ull d;
    asm("mov.b64 %0, {%1, %1};" : "=l"(d) : "f"(x));
    return d;
}
__device__ __forceinline__ float2 unpack2(ull v) {
    float2 r;
    asm("mov.b64 {%0, %1}, %2;" : "=f"(r.x), "=f"(r.y) : "l"(v));
    return r;
}

// =================================================================================
// Kernel 1: pre-projection GEMM
//   C[m][n] = X_row(m) . W[:,n] + bias[n],   m = t*32+b (M=16384), n in [0,1024)
//   n < 512 -> forward (W_f rows 0..511), n >= 512 -> backward (W_b rows 0..511)
//   Tiling: BM=128, BN=128, BK=8, 256 threads, 8x8 micro-tile, f32x2 accumulation
//   grid = (8, 128)
// =================================================================================
__global__ __launch_bounds__(256) void pre_gemm(
    const float* __restrict__ X,
    const float* __restrict__ Wf, const float* __restrict__ bf,
    const float* __restrict__ Wb, const float* __restrict__ bb)
{
    __shared__ float As[8][132];   // [k][m]  (transposed A tile)
    __shared__ float Bs[8][136];   // [k][n]

    // reset the recurrence barrier counter once per launch sequence (runs before recur)
    if (blockIdx.x == 0 && blockIdx.y == 0 && threadIdx.x == 0) g_bar = 0u;

    const int tid = threadIdx.x;
    const int m0 = blockIdx.y * 128;
    const int n0 = blockIdx.x * 128;          // 0..1023
    const int dir = n0 >> 9;
    const int c0 = n0 & 511;
    const float* Bmat = dir ? Wb : Wf;
    const float* bias = dir ? bb : bf;

    // A tile loader: each thread loads one float4 along K of one M-row
    const int ar  = tid >> 1;                 // 0..127 (m within tile)
    const int akq = (tid & 1) * 4;            // 0 or 4 (k offset)
    const int am  = m0 + ar;                  // global m = t*32 + b
    const float* Arow = X + ((size_t)(am & 31) * 512 + (size_t)(am >> 5)) * 512;

    // B tile loader: float4 along N
    const int bkk = tid >> 5;                 // 0..7
    const int bnq = (tid & 31) * 4;           // 0..124

    const int ty = tid >> 4;                  // 0..15 -> m micro base ty*8
    const int tx = tid & 15;                  // 0..15 -> n micro base tx*8

    ull acc[4][8];
    #pragma unroll
    for (int i = 0; i < 4; ++i)
        #pragma unroll
        for (int j = 0; j < 8; ++j) acc[i][j] = 0ull;

    for (int k0 = 0; k0 < 512; k0 += 8) {
        float4 av = *(const float4*)(Arow + k0 + akq);
        float4 bv = *(const float4*)(Bmat + (size_t)(k0 + bkk) * 512 + c0 + bnq);
        __syncthreads();
        As[akq + 0][ar] = av.x;
        As[akq + 1][ar] = av.y;
        As[akq + 2][ar] = av.z;
        As[akq + 3][ar] = av.w;
        *(float4*)&Bs[bkk][bnq] = bv;
        __syncthreads();

        #pragma unroll
        for (int k = 0; k < 8; ++k) {
            ulonglong2 a01 = *(const ulonglong2*)&As[k][ty * 8];
            ulonglong2 a23 = *(const ulonglong2*)&As[k][ty * 8 + 4];
            float4 bA = *(const float4*)&Bs[k][tx * 8];
            float4 bB = *(const float4*)&Bs[k][tx * 8 + 4];
            ull bd[8];
            bd[0] = pack2(bA.x); bd[1] = pack2(bA.y);
            bd[2] = pack2(bA.z); bd[3] = pack2(bA.w);
            bd[4] = pack2(bB.x); bd[5] = pack2(bB.y);
            bd[6] = pack2(bB.z); bd[7] = pack2(bB.w);
            #pragma unroll
            for (int j = 0; j < 8; ++j) {
                acc[0][j] = ffma2(a01.x, bd[j], acc[0][j]);
                acc[1][j] = ffma2(a01.y, bd[j], acc[1][j]);
                acc[2][j] = ffma2(a23.x, bd[j], acc[2][j]);
                acc[3][j] = ffma2(a23.y, bd[j], acc[3][j]);
            }
        }
    }

    // epilogue: add bias, scatter rows (m -> t,b), contiguous in c
    const int cg = c0 + tx * 8;
    float4 bl = *(const float4*)(bias + cg);
    float4 bh = *(const float4*)(bias + cg + 4);
    #pragma unroll
    for (int mp = 0; mp < 4; ++mp) {
        float2 v[8];
        #pragma unroll
        for (int j = 0; j < 8; ++j) v[j] = unpack2(acc[mp][j]);
        #pragma unroll
        for (int p = 0; p < 2; ++p) {
            int m = m0 + ty * 8 + mp * 2 + p;
            int tt = m >> 5, bb2 = m & 31;
            float* dst = g_pre + ((size_t)dir * 512 + tt) * 16384 + (size_t)bb2 * 512 + cg;
            float4 o0, o1;
            o0.x = (p ? v[0].y : v[0].x) + bl.x;
            o0.y = (p ? v[1].y : v[1].x) + bl.y;
            o0.z = (p ? v[2].y : v[2].x) + bl.z;
            o0.w = (p ? v[3].y : v[3].x) + bl.w;
            o1.x = (p ? v[4].y : v[4].x) + bh.x;
            o1.y = (p ? v[5].y : v[5].x) + bh.y;
            o1.z = (p ? v[6].y : v[6].x) + bh.z;
            o1.w = (p ? v[7].y : v[7].x) + bh.w;
            *(float4*)dst = o0;
            *(float4*)(dst + 4) = o1;
        }
    }
}

// =================================================================================
// Kernel 2: persistent bidirectional recurrence
//   128 CTAs = 2 dirs x 64 column-slices (8 cols each), 256 threads
//   Wh slice (512x8) lives in smem for all 512 steps; H_prev streamed from L2 (.cg)
//   grid-wide barrier per step via monotonic atomic counter + acquire-load spin
// =================================================================================
__global__ __launch_bounds__(256) void recur_kernel(
    const float* __restrict__ Wf, const float* __restrict__ Wb)
{
    __shared__ float s_w[8 * 516];   // [cl][k], padded row stride 516

    const int dir = blockIdx.x & 1;
    const int slice = blockIdx.x >> 1;     // 0..63
    const int c0 = slice * 8;
    const float* W = dir ? Wb : Wf;

    // load Wh slice once (W rows 512..1023 are Wh)
    for (int idx = threadIdx.x; idx < 4096; idx += 256) {
        int k = idx >> 3, cl = idx & 7;
        s_w[cl * 516 + k] = W[(size_t)(512 + k) * 512 + c0 + cl];
    }
    __syncthreads();

    const int b = threadIdx.x >> 3;        // 0..31
    const int cl = threadIdx.x & 7;        // 0..7
    const float4* wrow = (const float4*)(s_w + cl * 516);
    const unsigned grid = gridDim.x;

    for (int s = 0; s < 512; ++s) {
        const int t = dir ? (511 - s) : s;
        float4 acc4 = make_float4(0.f, 0.f, 0.f, 0.f);

        if (s > 0) {
            const int tp = dir ? (t + 1) : (t - 1);
            const float4* hrow =
                (const float4*)(g_hs + ((size_t)tp * 32 + b) * 1024 + (size_t)dir * 512);
            #pragma unroll 8
            for (int kk = 0; kk < 128; ++kk) {
                float4 h4 = __ldcg(hrow + kk);
                float4 w4 = wrow[kk];
                acc4.x = fmaf(h4.x, w4.x, acc4.x);
                acc4.y = fmaf(h4.y, w4.y, acc4.y);
                acc4.z = fmaf(h4.z, w4.z, acc4.z);
                acc4.w = fmaf(h4.w, w4.w, acc4.w);
            }
        }
        float acc = (acc4.x + acc4.y) + (acc4.z + acc4.w);
        acc += __ldcg(&g_pre[((size_t)dir * 512 + t) * 16384 + (size_t)b * 512 + c0 + cl]);
        float h = tanhf(acc);
        __stcg(&g_hs[((size_t)t * 32 + b) * 1024 + (size_t)dir * 512 + c0 + cl], h);

        // ---- grid-wide barrier (monotonic counter, no reset between steps) ----
        __syncthreads();
        if (threadIdx.x == 0) {
            __threadfence();
            atomicAdd(&g_bar, 1u);
            const unsigned target = (unsigned)(s + 1) * grid;
            unsigned v;
            do {
                asm volatile("ld.acquire.gpu.global.u32 %0, [%1];"
                             : "=r"(v) : "l"(&g_bar) : "memory");
            } while (v < target);
        }
        __syncthreads();
    }
}

// =================================================================================
// Kernel 3: output GEMM
//   out[b][t][o] = HS[m=t*32+b][:1024] . W_o[:, o] + b_o[o]
//   Same tiling as pre_gemm; A = g_hs (contiguous rows of 1024). grid = (4, 128)
// =================================================================================
__global__ __launch_bounds__(256) void out_gemm(
    const float* __restrict__ Wo, const float* __restrict__ bo,
    float* __restrict__ out)
{
    __shared__ float As[8][132];
    __shared__ float Bs[8][136];

    const int tid = threadIdx.x;
    const int m0 = blockIdx.y * 128;
    const int n0 = blockIdx.x * 128;          // 0..511

    const int ar  = tid >> 1;
    const int akq = (tid & 1) * 4;
    const float* Arow = g_hs + (size_t)(m0 + ar) * 1024;

    const int bkk = tid >> 5;
    const int bnq = (tid & 31) * 4;

    const int ty = tid >> 4;
    const int tx = tid & 15;

    ull acc[4][8];
    #pragma unroll
    for (int i = 0; i < 4; ++i)
        #pragma unroll
        for (int j = 0; j < 8; ++j) acc[i][j] = 0ull;

    for (int k0 = 0; k0 < 1024; k0 += 8) {
        float4 av = *(const float4*)(Arow + k0 + akq);
        float4 bv = *(const float4*)(Wo + (size_t)(k0 + bkk) * 512 + n0 + bnq);
        __syncthreads();
        As[akq + 0][ar] = av.x;
        As[akq + 1][ar] = av.y;
        As[akq + 2][ar] = av.z;
        As[akq + 3][ar] = av.w;
        *(float4*)&Bs[bkk][bnq] = bv;
        __syncthreads();

        #pragma unroll
        for (int k = 0; k < 8; ++k) {
            ulonglong2 a01 = *(const ulonglong2*)&As[k][ty * 8];
            ulonglong2 a23 = *(const ulonglong2*)&As[k][ty * 8 + 4];
            float4 bA = *(const float4*)&Bs[k][tx * 8];
            float4 bB = *(const float4*)&Bs[k][tx * 8 + 4];
            ull bd[8];
            bd[0] = pack2(bA.x); bd[1] = pack2(bA.y);
            bd[2] = pack2(bA.z); bd[3] = pack2(bA.w);
            bd[4] = pack2(bB.x); bd[5] = pack2(bB.y);
            bd[6] = pack2(bB.z); bd[7] = pack2(bB.w);
            #pragma unroll
            for (int j = 0; j < 8; ++j) {
                acc[0][j] = ffma2(a01.x, bd[j], acc[0][j]);
                acc[1][j] = ffma2(a01.y, bd[j], acc[1][j]);
                acc[2][j] = ffma2(a23.x, bd[j], acc[2][j]);
                acc[3][j] = ffma2(a23.y, bd[j], acc[3][j]);
            }
        }
    }

    const int og = n0 + tx * 8;
    float4 bl = *(const float4*)(bo + og);
    float4 bh = *(const float4*)(bo + og + 4);
    #pragma unroll
    for (int mp = 0; mp < 4; ++mp) {
        float2 v[8];
        #pragma unroll
        for (int j = 0; j < 8; ++j) v[j] = unpack2(acc[mp][j]);
        #pragma unroll
        for (int p = 0; p < 2; ++p) {
            int m = m0 + ty * 8 + mp * 2 + p;
            int tt = m >> 5, bb2 = m & 31;
            float* dst = out + ((size_t)bb2 * 512 + tt) * 512 + og;
            float4 o0, o1;
            o0.x = (p ? v[0].y : v[0].x) + bl.x;
            o0.y = (p ? v[1].y : v[1].x) + bl.y;
            o0.z = (p ? v[2].y : v[2].x) + bl.z;
            o0.w = (p ? v[3].y : v[3].x) + bl.w;
            o1.x = (p ? v[4].y : v[4].x) + bh.x;
            o1.y = (p ? v[5].y : v[5].x) + bh.y;
            o1.z = (p ? v[6].y : v[6].x) + bh.z;
            o1.w = (p ? v[7].y : v[7].x) + bh.w;
            *(float4*)dst = o0;
            *(float4*)(dst + 4) = o1;
        }
    }
}

// =================================================================================
extern "C" void kernel_launch(void* const* d_in, const int* in_sizes, int n_in,
                              void* d_out, int out_size)
{
    const float* X  = (const float*)d_in[0];
    const float* Wf = (const float*)d_in[1];
    const float* bf = (const float*)d_in[2];
    const float* Wb = (const float*)d_in[3];
    const float* bb = (const float*)d_in[4];
    const float* Wo = (const float*)d_in[5];
    const float* bo = (const float*)d_in[6];
    float* out = (float*)d_out;

    pre_gemm<<<dim3(8, 128), 256>>>(X, Wf, bf, Wb, bb);
    recur_kernel<<<128, 256>>>(Wf, Wb);
    out_gemm<<<dim3(4, 128), 256>>>(Wo, bo, out);
}

// round 2
// speedup vs baseline: 1.6644x; 1.6644x over previous
#include <cuda_runtime.h>
#include <cuda_bf16.h>
#include <math.h>

typedef unsigned long long ull;

// ---------------- scratch (static device globals; no allocation) ----------------
__device__ float g_pre[2u * 512u * 32u * 512u];   // [dir][t][b][c] 64MB
__device__ float g_hs[512u * 32u * 1024u];        // [t][b][dir*512+c] 64MB
__device__ unsigned int g_bar2[2];                // per-direction barrier counters

// ---------------- f32x2 helpers ----------------
__device__ __forceinline__ ull ffma2(ull a, ull b, ull c) {
    ull d;
    asm("fma.rn.f32x2 %0, %1, %2, %3;" : "=l"(d) : "l"(a), "l"(b), "l"(c));
    return d;
}
__device__ __forceinline__ ull pack2(float x) {
    ull d;
    asm("mov.b64 %0, {%1, %1};" : "=l"(d) : "f"(x));
    return d;
}
__device__ __forceinline__ float2 unpack2(ull v) {
    float2 r;
    asm("mov.b64 {%0, %1}, %2;" : "=f"(r.x), "=f"(r.y) : "l"(v));
    return r;
}

// =================================================================================
// Kernel 1: pre-projection GEMM  (unchanged from R1 except barrier reset)
// =================================================================================
__global__ __launch_bounds__(256) void pre_gemm(
    const float* __restrict__ X,
    const float* __restrict__ Wf, const float* __restrict__ bf,
    const float* __restrict__ Wb, const float* __restrict__ bb)
{
    __shared__ float As[8][132];
    __shared__ float Bs[8][136];

    if (blockIdx.x == 0 && blockIdx.y == 0 && threadIdx.x == 0) {
        g_bar2[0] = 0u; g_bar2[1] = 0u;
    }

    const int tid = threadIdx.x;
    const int m0 = blockIdx.y * 128;
    const int n0 = blockIdx.x * 128;
    const int dir = n0 >> 9;
    const int c0 = n0 & 511;
    const float* Bmat = dir ? Wb : Wf;
    const float* bias = dir ? bb : bf;

    const int ar  = tid >> 1;
    const int akq = (tid & 1) * 4;
    const int am  = m0 + ar;
    const float* Arow = X + ((size_t)(am & 31) * 512 + (size_t)(am >> 5)) * 512;

    const int bkk = tid >> 5;
    const int bnq = (tid & 31) * 4;

    const int ty = tid >> 4;
    const int tx = tid & 15;

    ull acc[4][8];
    #pragma unroll
    for (int i = 0; i < 4; ++i)
        #pragma unroll
        for (int j = 0; j < 8; ++j) acc[i][j] = 0ull;

    for (int k0 = 0; k0 < 512; k0 += 8) {
        float4 av = *(const float4*)(Arow + k0 + akq);
        float4 bv = *(const float4*)(Bmat + (size_t)(k0 + bkk) * 512 + c0 + bnq);
        __syncthreads();
        As[akq + 0][ar] = av.x;
        As[akq + 1][ar] = av.y;
        As[akq + 2][ar] = av.z;
        As[akq + 3][ar] = av.w;
        *(float4*)&Bs[bkk][bnq] = bv;
        __syncthreads();

        #pragma unroll
        for (int k = 0; k < 8; ++k) {
            ulonglong2 a01 = *(const ulonglong2*)&As[k][ty * 8];
            ulonglong2 a23 = *(const ulonglong2*)&As[k][ty * 8 + 4];
            float4 bA = *(const float4*)&Bs[k][tx * 8];
            float4 bB = *(const float4*)&Bs[k][tx * 8 + 4];
            ull bd[8];
            bd[0] = pack2(bA.x); bd[1] = pack2(bA.y);
            bd[2] = pack2(bA.z); bd[3] = pack2(bA.w);
            bd[4] = pack2(bB.x); bd[5] = pack2(bB.y);
            bd[6] = pack2(bB.z); bd[7] = pack2(bB.w);
            #pragma unroll
            for (int j = 0; j < 8; ++j) {
                acc[0][j] = ffma2(a01.x, bd[j], acc[0][j]);
                acc[1][j] = ffma2(a01.y, bd[j], acc[1][j]);
                acc[2][j] = ffma2(a23.x, bd[j], acc[2][j]);
                acc[3][j] = ffma2(a23.y, bd[j], acc[3][j]);
            }
        }
    }

    const int cg = c0 + tx * 8;
    float4 bl = *(const float4*)(bias + cg);
    float4 bh = *(const float4*)(bias + cg + 4);
    #pragma unroll
    for (int mp = 0; mp < 4; ++mp) {
        float2 v[8];
        #pragma unroll
        for (int j = 0; j < 8; ++j) v[j] = unpack2(acc[mp][j]);
        #pragma unroll
        for (int p = 0; p < 2; ++p) {
            int m = m0 + ty * 8 + mp * 2 + p;
            int tt = m >> 5, bb2 = m & 31;
            float* dst = g_pre + ((size_t)dir * 512 + tt) * 16384 + (size_t)bb2 * 512 + cg;
            float4 o0, o1;
            o0.x = (p ? v[0].y : v[0].x) + bl.x;
            o0.y = (p ? v[1].y : v[1].x) + bl.y;
            o0.z = (p ? v[2].y : v[2].x) + bl.z;
            o0.w = (p ? v[3].y : v[3].x) + bl.w;
            o1.x = (p ? v[4].y : v[4].x) + bh.x;
            o1.y = (p ? v[5].y : v[5].x) + bh.y;
            o1.z = (p ? v[6].y : v[6].x) + bh.z;
            o1.w = (p ? v[7].y : v[7].x) + bh.w;
            *(float4*)dst = o0;
            *(float4*)(dst + 4) = o1;
        }
    }
}

// =================================================================================
// Kernel 2: persistent bidirectional recurrence (v2)
//   128 CTAs = 2 dirs x 64 column-slices (8 cols each), 256 threads
//   Per step: stage full h_prev (32x512, 64KB) into smem cooperatively (coalesced),
//   then f32x2 mat-vec from smem. Per-direction grid barrier with REDG + backoff.
//   Dynamic smem: s_w 8x516 + s_h 32x520 = 83KB
// =================================================================================
__global__ __launch_bounds__(256) void recur_kernel(
    const float* __restrict__ Wf, const float* __restrict__ Wb)
{
    extern __shared__ float smem[];
    float* s_w = smem;               // [cl][k], stride 516
    float* s_h = smem + 8 * 516;     // [b][k],  stride 520

    const int tid = threadIdx.x;
    const int dir = blockIdx.x & 1;
    const int slice = blockIdx.x >> 1;     // 0..63
    const int c0 = slice * 8;
    const float* W = dir ? Wb : Wf;

    // load Wh slice once (W rows 512..1023 are Wh)
    for (int idx = tid; idx < 4096; idx += 256) {
        int k = idx >> 3, cl = idx & 7;
        s_w[cl * 516 + k] = W[(size_t)(512 + k) * 512 + c0 + cl];
    }
    __syncthreads();

    const int b  = tid >> 3;        // 0..31
    const int cl = tid & 7;         // 0..7
    unsigned int* bar = &g_bar2[dir];

    for (int s = 0; s < 512; ++s) {
        const int t = dir ? (511 - s) : s;

        // prefetch pre-activation early
        float pre = __ldcg(&g_pre[((size_t)dir * 512 + t) * 16384 +
                                  (size_t)b * 512 + c0 + cl]);

        float acc = 0.f;
        if (s > 0) {
            const int tp = dir ? (t + 1) : (t - 1);
            // ---- stage h_prev[32][512] (this dir's half) into smem, coalesced ----
            #pragma unroll 4
            for (int idx = tid; idx < 4096; idx += 256) {
                int sb  = idx >> 7;        // 0..31
                int off = idx & 127;       // float4 index within 512-float row
                float4 v = __ldcg((const float4*)(g_hs +
                              ((size_t)tp * 32 + sb) * 1024 + (size_t)dir * 512) + off);
                *(float4*)&s_h[sb * 520 + off * 4] = v;
            }
            __syncthreads();

            // ---- mat-vec from smem: acc = h_row(b) . w_col(cl), f32x2 ----
            const ulonglong2* hp = (const ulonglong2*)(s_h + b * 520);
            const ulonglong2* wp = (const ulonglong2*)(s_w + cl * 516);
            ull acc_a = 0ull, acc_b = 0ull;
            #pragma unroll 8
            for (int kk = 0; kk < 128; ++kk) {
                ulonglong2 h2 = hp[kk];
                ulonglong2 w2 = wp[kk];
                acc_a = ffma2(h2.x, w2.x, acc_a);
                acc_b = ffma2(h2.y, w2.y, acc_b);
            }
            float2 ra = unpack2(acc_a), rb = unpack2(acc_b);
            acc = (ra.x + rb.x) + (ra.y + rb.y);
            __syncthreads();   // protect s_h before next step's staging
        }

        float h = tanhf(acc + pre);
        __stcg(&g_hs[((size_t)t * 32 + b) * 1024 + (size_t)dir * 512 + c0 + cl], h);

        // ---- per-direction grid barrier (monotonic counter) ----
        if (s < 511) {
            if (tid == 0) {
                asm volatile("red.release.gpu.global.add.u32 [%0], 1;"
                             :: "l"(bar) : "memory");
                const unsigned target = (unsigned)(s + 1) * 64u;
                unsigned v;
                for (;;) {
                    asm volatile("ld.acquire.gpu.global.u32 %0, [%1];"
                                 : "=r"(v) : "l"(bar) : "memory");
                    if (v >= target) break;
                    __nanosleep(64);
                }
            }
            __syncthreads();
        }
    }
}

// =================================================================================
// Kernel 3: output GEMM (unchanged)
// =================================================================================
__global__ __launch_bounds__(256) void out_gemm(
    const float* __restrict__ Wo, const float* __restrict__ bo,
    float* __restrict__ out)
{
    __shared__ float As[8][132];
    __shared__ float Bs[8][136];

    const int tid = threadIdx.x;
    const int m0 = blockIdx.y * 128;
    const int n0 = blockIdx.x * 128;

    const int ar  = tid >> 1;
    const int akq = (tid & 1) * 4;
    const float* Arow = g_hs + (size_t)(m0 + ar) * 1024;

    const int bkk = tid >> 5;
    const int bnq = (tid & 31) * 4;

    const int ty = tid >> 4;
    const int tx = tid & 15;

    ull acc[4][8];
    #pragma unroll
    for (int i = 0; i < 4; ++i)
        #pragma unroll
        for (int j = 0; j < 8; ++j) acc[i][j] = 0ull;

    for (int k0 = 0; k0 < 1024; k0 += 8) {
        float4 av = *(const float4*)(Arow + k0 + akq);
        float4 bv = *(const float4*)(Wo + (size_t)(k0 + bkk) * 512 + n0 + bnq);
        __syncthreads();
        As[akq + 0][ar] = av.x;
        As[akq + 1][ar] = av.y;
        As[akq + 2][ar] = av.z;
        As[akq + 3][ar] = av.w;
        *(float4*)&Bs[bkk][bnq] = bv;
        __syncthreads();

        #pragma unroll
        for (int k = 0; k < 8; ++k) {
            ulonglong2 a01 = *(const ulonglong2*)&As[k][ty * 8];
            ulonglong2 a23 = *(const ulonglong2*)&As[k][ty * 8 + 4];
            float4 bA = *(const float4*)&Bs[k][tx * 8];
            float4 bB = *(const float4*)&Bs[k][tx * 8 + 4];
            ull bd[8];
            bd[0] = pack2(bA.x); bd[1] = pack2(bA.y);
            bd[2] = pack2(bA.z); bd[3] = pack2(bA.w);
            bd[4] = pack2(bB.x); bd[5] = pack2(bB.y);
            bd[6] = pack2(bB.z); bd[7] = pack2(bB.w);
            #pragma unroll
            for (int j = 0; j < 8; ++j) {
                acc[0][j] = ffma2(a01.x, bd[j], acc[0][j]);
                acc[1][j] = ffma2(a01.y, bd[j], acc[1][j]);
                acc[2][j] = ffma2(a23.x, bd[j], acc[2][j]);
                acc[3][j] = ffma2(a23.y, bd[j], acc[3][j]);
            }
        }
    }

    const int og = n0 + tx * 8;
    float4 bl = *(const float4*)(bo + og);
    float4 bh = *(const float4*)(bo + og + 4);
    #pragma unroll
    for (int mp = 0; mp < 4; ++mp) {
        float2 v[8];
        #pragma unroll
        for (int j = 0; j < 8; ++j) v[j] = unpack2(acc[mp][j]);
        #pragma unroll
        for (int p = 0; p < 2; ++p) {
            int m = m0 + ty * 8 + mp * 2 + p;
            int tt = m >> 5, bb2 = m & 31;
            float* dst = out + ((size_t)bb2 * 512 + tt) * 512 + og;
            float4 o0, o1;
            o0.x = (p ? v[0].y : v[0].x) + bl.x;
            o0.y = (p ? v[1].y : v[1].x) + bl.y;
            o0.z = (p ? v[2].y : v[2].x) + bl.z;
            o0.w = (p ? v[3].y : v[3].x) + bl.w;
            o1.x = (p ? v[4].y : v[4].x) + bh.x;
            o1.y = (p ? v[5].y : v[5].x) + bh.y;
            o1.z = (p ? v[6].y : v[6].x) + bh.z;
            o1.w = (p ? v[7].y : v[7].x) + bh.w;
            *(float4*)dst = o0;
            *(float4*)(dst + 4) = o1;
        }
    }
}

// =================================================================================
extern "C" void kernel_launch(void* const* d_in, const int* in_sizes, int n_in,
                              void* d_out, int out_size)
{
    const float* X  = (const float*)d_in[0];
    const float* Wf = (const float*)d_in[1];
    const float* bf = (const float*)d_in[2];
    const float* Wb = (const float*)d_in[3];
    const float* bb = (const float*)d_in[4];
    const float* Wo = (const float*)d_in[5];
    const float* bo = (const float*)d_in[6];
    float* out = (float*)d_out;

    const int recur_smem = (8 * 516 + 32 * 520) * (int)sizeof(float);  // 83072 B
    cudaFuncSetAttribute(recur_kernel,
                         cudaFuncAttributeMaxDynamicSharedMemorySize, recur_smem);

    pre_gemm<<<dim3(8, 128), 256>>>(X, Wf, bf, Wb, bb);
    recur_kernel<<<128, 256, recur_smem>>>(Wf, Wb);
    out_gemm<<<dim3(4, 128), 256>>>(Wo, bo, out);
}

// round 3
// speedup vs baseline: 2.8120x; 1.6895x over previous
#include <cuda_runtime.h>
#include <cuda_bf16.h>
#include <math.h>

typedef unsigned long long ull;

// ---------------- scratch (static device globals; no allocation) ----------------
__device__ float g_pre[2u * 512u * 32u * 512u];   // [dir][t][b][c] 64MB
__device__ float g_hs[512u * 32u * 1024u];        // [t][b][dir*512+c] 64MB
__device__ unsigned int g_bar2[2];                // per-direction barrier counters

// ---------------- f32x2 helpers ----------------
__device__ __forceinline__ ull ffma2(ull a, ull b, ull c) {
    ull d;
    asm("fma.rn.f32x2 %0, %1, %2, %3;" : "=l"(d) : "l"(a), "l"(b), "l"(c));
    return d;
}
__device__ __forceinline__ ull pack2(float x) {
    ull d;
    asm("mov.b64 %0, {%1, %1};" : "=l"(d) : "f"(x));
    return d;
}
__device__ __forceinline__ ull packab(float a, float b) {
    ull d;
    asm("mov.b64 %0, {%1, %2};" : "=l"(d) : "f"(a), "f"(b));
    return d;
}
__device__ __forceinline__ float2 unpack2(ull v) {
    float2 r;
    asm("mov.b64 {%0, %1}, %2;" : "=f"(r.x), "=f"(r.y) : "l"(v));
    return r;
}

// =================================================================================
// Kernel 1: pre-projection GEMM  (register double-buffered)
// =================================================================================
__global__ __launch_bounds__(256) void pre_gemm(
    const float* __restrict__ X,
    const float* __restrict__ Wf, const float* __restrict__ bf,
    const float* __restrict__ Wb, const float* __restrict__ bb)
{
    __shared__ float As[8][132];
    __shared__ float Bs[8][136];

    if (blockIdx.x == 0 && blockIdx.y == 0 && threadIdx.x == 0) {
        g_bar2[0] = 0u; g_bar2[1] = 0u;
    }

    const int tid = threadIdx.x;
    const int m0 = blockIdx.y * 128;
    const int n0 = blockIdx.x * 128;
    const int dir = n0 >> 9;
    const int c0 = n0 & 511;
    const float* Bmat = dir ? Wb : Wf;
    const float* bias = dir ? bb : bf;

    const int ar  = tid >> 1;
    const int akq = (tid & 1) * 4;
    const int am  = m0 + ar;
    const float* Arow = X + ((size_t)(am & 31) * 512 + (size_t)(am >> 5)) * 512;

    const int bkk = tid >> 5;
    const int bnq = (tid & 31) * 4;

    const int ty = tid >> 4;
    const int tx = tid & 15;

    ull acc[4][8];
    #pragma unroll
    for (int i = 0; i < 4; ++i)
        #pragma unroll
        for (int j = 0; j < 8; ++j) acc[i][j] = 0ull;

    float4 av = *(const float4*)(Arow + akq);
    float4 bv = *(const float4*)(Bmat + (size_t)bkk * 512 + c0 + bnq);

    for (int k0 = 0; k0 < 512; k0 += 8) {
        __syncthreads();
        As[akq + 0][ar] = av.x;
        As[akq + 1][ar] = av.y;
        As[akq + 2][ar] = av.z;
        As[akq + 3][ar] = av.w;
        *(float4*)&Bs[bkk][bnq] = bv;
        __syncthreads();

        if (k0 + 8 < 512) {
            av = *(const float4*)(Arow + k0 + 8 + akq);
            bv = *(const float4*)(Bmat + (size_t)(k0 + 8 + bkk) * 512 + c0 + bnq);
        }

        #pragma unroll
        for (int k = 0; k < 8; ++k) {
            ulonglong2 a01 = *(const ulonglong2*)&As[k][ty * 8];
            ulonglong2 a23 = *(const ulonglong2*)&As[k][ty * 8 + 4];
            float4 bA = *(const float4*)&Bs[k][tx * 8];
            float4 bB = *(const float4*)&Bs[k][tx * 8 + 4];
            ull bd[8];
            bd[0] = pack2(bA.x); bd[1] = pack2(bA.y);
            bd[2] = pack2(bA.z); bd[3] = pack2(bA.w);
            bd[4] = pack2(bB.x); bd[5] = pack2(bB.y);
            bd[6] = pack2(bB.z); bd[7] = pack2(bB.w);
            #pragma unroll
            for (int j = 0; j < 8; ++j) {
                acc[0][j] = ffma2(a01.x, bd[j], acc[0][j]);
                acc[1][j] = ffma2(a01.y, bd[j], acc[1][j]);
                acc[2][j] = ffma2(a23.x, bd[j], acc[2][j]);
                acc[3][j] = ffma2(a23.y, bd[j], acc[3][j]);
            }
        }
    }

    const int cg = c0 + tx * 8;
    float4 bl = *(const float4*)(bias + cg);
    float4 bh = *(const float4*)(bias + cg + 4);
    #pragma unroll
    for (int mp = 0; mp < 4; ++mp) {
        float2 v[8];
        #pragma unroll
        for (int j = 0; j < 8; ++j) v[j] = unpack2(acc[mp][j]);
        #pragma unroll
        for (int p = 0; p < 2; ++p) {
            int m = m0 + ty * 8 + mp * 2 + p;
            int tt = m >> 5, bb2 = m & 31;
            float* dst = g_pre + ((size_t)dir * 512 + tt) * 16384 + (size_t)bb2 * 512 + cg;
            float4 o0, o1;
            o0.x = (p ? v[0].y : v[0].x) + bl.x;
            o0.y = (p ? v[1].y : v[1].x) + bl.y;
            o0.z = (p ? v[2].y : v[2].x) + bl.z;
            o0.w = (p ? v[3].y : v[3].x) + bl.w;
            o1.x = (p ? v[4].y : v[4].x) + bh.x;
            o1.y = (p ? v[5].y : v[5].x) + bh.y;
            o1.z = (p ? v[6].y : v[6].x) + bh.z;
            o1.w = (p ? v[7].y : v[7].x) + bh.w;
            *(float4*)dst = o0;
            *(float4*)(dst + 4) = o1;
        }
    }
}

// =================================================================================
// Kernel 2: persistent bidirectional recurrence (v3)
//   128 CTAs = 2 dirs x 64 slices (8 cols), 512 threads.
//   Wh slice in REGISTERS (thread = (col, ks, bgroup): 64 weights = 32 f32x2).
//   h staged L2->smem in 4 chunks of 128 k, pipelined with FFMA compute.
//   8-way ks partial reduce through smem; per-direction grid barrier.
// =================================================================================
__global__ __launch_bounds__(512) void recur_kernel(
    const float* __restrict__ Wf, const float* __restrict__ Wb)
{
    extern __shared__ float smem[];
    float* s_h   = smem;               // [32][520]
    float* s_red = smem + 32 * 520;    // [8][256]

    const int tid = threadIdx.x;
    const int dir = blockIdx.x & 1;
    const int slice = blockIdx.x >> 1;     // 0..63
    const int c0 = slice * 8;
    const float* W = dir ? Wb : Wf;

    const int c  = tid & 7;
    const int ks = (tid >> 3) & 7;
    const int b0 = (tid >> 6) * 4;

    // Wh column (c0+c), k-subset {ch*128 + ks*16 + 0..15 : ch=0..3} -> 32 f32x2 regs
    ull wreg[4][4][2];
    #pragma unroll
    for (int ch = 0; ch < 4; ++ch)
        #pragma unroll
        for (int kk = 0; kk < 4; ++kk) {
            int k = ch * 128 + ks * 16 + kk * 4;
            const float* wp = W + (size_t)(512 + k) * 512 + c0 + c;
            float w0 = wp[0], w1 = wp[512], w2 = wp[1024], w3 = wp[1536];
            wreg[ch][kk][0] = packab(w0, w1);
            wreg[ch][kk][1] = packab(w2, w3);
        }

    const int sb0  = tid >> 5;            // staging row for idx = tid      (0..15)
    const int sb1  = (tid + 512) >> 5;    // staging row for idx = tid+512  (16..31)
    const int soff = (tid & 31) * 4;      // float offset within 128-float chunk row

    unsigned int* bar = &g_bar2[dir];

    for (int s = 0; s < 512; ++s) {
        const int t = dir ? (511 - s) : s;

        float pre = 0.f;
        if (tid < 256)
            pre = __ldcg(&g_pre[((size_t)dir * 512 + t) * 16384 +
                                (size_t)(tid >> 3) * 512 + c0 + (tid & 7)]);

        float hval = 0.f;
        if (s == 0) {
            if (tid < 256) hval = tanhf(pre);
        } else {
            const int tp = dir ? (t + 1) : (t - 1);
            const float* hbase = g_hs + (size_t)tp * 32 * 1024 + dir * 512;

            // stage chunk 0
            {
                float4 v0 = __ldcg((const float4*)(hbase + sb0 * 1024 + soff));
                float4 v1 = __ldcg((const float4*)(hbase + sb1 * 1024 + soff));
                *(float4*)&s_h[sb0 * 520 + soff] = v0;
                *(float4*)&s_h[sb1 * 520 + soff] = v1;
            }
            __syncthreads();

            ull acc[4] = {0ull, 0ull, 0ull, 0ull};
            #pragma unroll
            for (int ch = 0; ch < 4; ++ch) {
                float4 n0, n1;
                if (ch < 3) {   // issue next chunk's loads before computing
                    n0 = __ldcg((const float4*)(hbase + sb0 * 1024 + (ch + 1) * 128 + soff));
                    n1 = __ldcg((const float4*)(hbase + sb1 * 1024 + (ch + 1) * 128 + soff));
                }
                #pragma unroll
                for (int j = 0; j < 4; ++j) {
                    const ulonglong2* hp =
                        (const ulonglong2*)&s_h[(b0 + j) * 520 + ch * 128 + ks * 16];
                    #pragma unroll
                    for (int kk = 0; kk < 4; ++kk) {
                        ulonglong2 h2 = hp[kk];
                        acc[j] = ffma2(h2.x, wreg[ch][kk][0], acc[j]);
                        acc[j] = ffma2(h2.y, wreg[ch][kk][1], acc[j]);
                    }
                }
                if (ch < 3) {
                    *(float4*)&s_h[sb0 * 520 + (ch + 1) * 128 + soff] = n0;
                    *(float4*)&s_h[sb1 * 520 + (ch + 1) * 128 + soff] = n1;
                    __syncthreads();
                }
            }

            // write ks-partials, reduce 8-way
            #pragma unroll
            for (int j = 0; j < 4; ++j) {
                float2 p = unpack2(acc[j]);
                s_red[ks * 256 + (b0 + j) * 8 + c] = p.x + p.y;
            }
            __syncthreads();
            if (tid < 256) {
                float sum = pre;
                #pragma unroll
                for (int k8 = 0; k8 < 8; ++k8) sum += s_red[k8 * 256 + tid];
                hval = tanhf(sum);
            }
        }

        if (tid < 256)
            __stcg(&g_hs[((size_t)t * 32 + (tid >> 3)) * 1024 +
                         dir * 512 + c0 + (tid & 7)], hval);

        if (s < 511) {
            __syncthreads();   // CTA-HB: all stores before thread0's release
            if (tid == 0) {
                asm volatile("red.release.gpu.global.add.u32 [%0], 1;"
                             :: "l"(bar) : "memory");
                const unsigned target = (unsigned)(s + 1) * 64u;
                unsigned v;
                for (;;) {
                    asm volatile("ld.acquire.gpu.global.u32 %0, [%1];"
                                 : "=r"(v) : "l"(bar) : "memory");
                    if (v >= target) break;
                    __nanosleep(32);
                }
            }
            __syncthreads();
        }
    }
}

// =================================================================================
// Kernel 3: output GEMM (register double-buffered)
// =================================================================================
__global__ __launch_bounds__(256) void out_gemm(
    const float* __restrict__ Wo, const float* __restrict__ bo,
    float* __restrict__ out)
{
    __shared__ float As[8][132];
    __shared__ float Bs[8][136];

    const int tid = threadIdx.x;
    const int m0 = blockIdx.y * 128;
    const int n0 = blockIdx.x * 128;

    const int ar  = tid >> 1;
    const int akq = (tid & 1) * 4;
    const float* Arow = g_hs + (size_t)(m0 + ar) * 1024;

    const int bkk = tid >> 5;
    const int bnq = (tid & 31) * 4;

    const int ty = tid >> 4;
    const int tx = tid & 15;

    ull acc[4][8];
    #pragma unroll
    for (int i = 0; i < 4; ++i)
        #pragma unroll
        for (int j = 0; j < 8; ++j) acc[i][j] = 0ull;

    float4 av = *(const float4*)(Arow + akq);
    float4 bv = *(const float4*)(Wo + (size_t)bkk * 512 + n0 + bnq);

    for (int k0 = 0; k0 < 1024; k0 += 8) {
        __syncthreads();
        As[akq + 0][ar] = av.x;
        As[akq + 1][ar] = av.y;
        As[akq + 2][ar] = av.z;
        As[akq + 3][ar] = av.w;
        *(float4*)&Bs[bkk][bnq] = bv;
        __syncthreads();

        if (k0 + 8 < 1024) {
            av = *(const float4*)(Arow + k0 + 8 + akq);
            bv = *(const float4*)(Wo + (size_t)(k0 + 8 + bkk) * 512 + n0 + bnq);
        }

        #pragma unroll
        for (int k = 0; k < 8; ++k) {
            ulonglong2 a01 = *(const ulonglong2*)&As[k][ty * 8];
            ulonglong2 a23 = *(const ulonglong2*)&As[k][ty * 8 + 4];
            float4 bA = *(const float4*)&Bs[k][tx * 8];
            float4 bB = *(const float4*)&Bs[k][tx * 8 + 4];
            ull bd[8];
            bd[0] = pack2(bA.x); bd[1] = pack2(bA.y);
            bd[2] = pack2(bA.z); bd[3] = pack2(bA.w);
            bd[4] = pack2(bB.x); bd[5] = pack2(bB.y);
            bd[6] = pack2(bB.z); bd[7] = pack2(bB.w);
            #pragma unroll
            for (int j = 0; j < 8; ++j) {
                acc[0][j] = ffma2(a01.x, bd[j], acc[0][j]);
                acc[1][j] = ffma2(a01.y, bd[j], acc[1][j]);
                acc[2][j] = ffma2(a23.x, bd[j], acc[2][j]);
                acc[3][j] = ffma2(a23.y, bd[j], acc[3][j]);
            }
        }
    }

    const int og = n0 + tx * 8;
    float4 bl = *(const float4*)(bo + og);
    float4 bh = *(const float4*)(bo + og + 4);
    #pragma unroll
    for (int mp = 0; mp < 4; ++mp) {
        float2 v[8];
        #pragma unroll
        for (int j = 0; j < 8; ++j) v[j] = unpack2(acc[mp][j]);
        #pragma unroll
        for (int p = 0; p < 2; ++p) {
            int m = m0 + ty * 8 + mp * 2 + p;
            int tt = m >> 5, bb2 = m & 31;
            float* dst = out + ((size_t)bb2 * 512 + tt) * 512 + og;
            float4 o0, o1;
            o0.x = (p ? v[0].y : v[0].x) + bl.x;
            o0.y = (p ? v[1].y : v[1].x) + bl.y;
            o0.z = (p ? v[2].y : v[2].x) + bl.z;
            o0.w = (p ? v[3].y : v[3].x) + bl.w;
            o1.x = (p ? v[4].y : v[4].x) + bh.x;
            o1.y = (p ? v[5].y : v[5].x) + bh.y;
            o1.z = (p ? v[6].y : v[6].x) + bh.z;
            o1.w = (p ? v[7].y : v[7].x) + bh.w;
            *(float4*)dst = o0;
            *(float4*)(dst + 4) = o1;
        }
    }
}

// =================================================================================
extern "C" void kernel_launch(void* const* d_in, const int* in_sizes, int n_in,
                              void* d_out, int out_size)
{
    const float* X  = (const float*)d_in[0];
    const float* Wf = (const float*)d_in[1];
    const float* bf = (const float*)d_in[2];
    const float* Wb = (const float*)d_in[3];
    const float* bb = (const float*)d_in[4];
    const float* Wo = (const float*)d_in[5];
    const float* bo = (const float*)d_in[6];
    float* out = (float*)d_out;

    const int recur_smem = (32 * 520 + 8 * 256) * (int)sizeof(float);  // 74752 B
    cudaFuncSetAttribute(recur_kernel,
                         cudaFuncAttributeMaxDynamicSharedMemorySize, recur_smem);

    pre_gemm<<<dim3(8, 128), 256>>>(X, Wf, bf, Wb, bb);
    recur_kernel<<<128, 512, recur_smem>>>(Wf, Wb);
    out_gemm<<<dim3(4, 128), 256>>>(Wo, bo, out);
}

// round 4
// speedup vs baseline: 3.3144x; 1.1787x over previous
#include <cuda_runtime.h>
#include <cuda_bf16.h>
#include <math.h>

typedef unsigned long long ull;

// ---------------- scratch (static device globals; no allocation) ----------------
__device__ float g_pre[2u * 512u * 32u * 512u];   // [dir][t][b][c] 64MB
__device__ float g_hs[512u * 32u * 1024u];        // [t][b][dir*512+c] 64MB
__device__ unsigned int g_bar8[8];                // per-(dir,group) barrier counters

// ---------------- f32x2 helpers ----------------
__device__ __forceinline__ ull ffma2(ull a, ull b, ull c) {
    ull d;
    asm("fma.rn.f32x2 %0, %1, %2, %3;" : "=l"(d) : "l"(a), "l"(b), "l"(c));
    return d;
}
__device__ __forceinline__ ull pack2(float x) {
    ull d;
    asm("mov.b64 %0, {%1, %1};" : "=l"(d) : "f"(x));
    return d;
}
__device__ __forceinline__ ull packab(float a, float b) {
    ull d;
    asm("mov.b64 %0, {%1, %2};" : "=l"(d) : "f"(a), "f"(b));
    return d;
}
__device__ __forceinline__ float2 unpack2(ull v) {
    float2 r;
    asm("mov.b64 {%0, %1}, %2;" : "=f"(r.x), "=f"(r.y) : "l"(v));
    return r;
}

// =================================================================================
// Kernel 1: pre-projection GEMM  (double-buffered smem, 1 sync per k-tile)
// =================================================================================
__global__ __launch_bounds__(256) void pre_gemm(
    const float* __restrict__ X,
    const float* __restrict__ Wf, const float* __restrict__ bf,
    const float* __restrict__ Wb, const float* __restrict__ bb)
{
    __shared__ float As[2][8][132];
    __shared__ float Bs[2][8][136];

    if (blockIdx.x == 0 && blockIdx.y == 0 && threadIdx.x < 8)
        g_bar8[threadIdx.x] = 0u;

    const int tid = threadIdx.x;
    const int m0 = blockIdx.y * 128;
    const int n0 = blockIdx.x * 128;
    const int dir = n0 >> 9;
    const int c0 = n0 & 511;
    const float* Bmat = dir ? Wb : Wf;
    const float* bias = dir ? bb : bf;

    const int ar  = tid >> 1;
    const int akq = (tid & 1) * 4;
    const int am  = m0 + ar;
    const float* Arow = X + ((size_t)(am & 31) * 512 + (size_t)(am >> 5)) * 512;

    const int bkk = tid >> 5;
    const int bnq = (tid & 31) * 4;

    const int ty = tid >> 4;
    const int tx = tid & 15;

    ull acc[4][8];
    #pragma unroll
    for (int i = 0; i < 4; ++i)
        #pragma unroll
        for (int j = 0; j < 8; ++j) acc[i][j] = 0ull;

    // prologue: fill buffer 0
    {
        float4 av = *(const float4*)(Arow + akq);
        float4 bv = *(const float4*)(Bmat + (size_t)bkk * 512 + c0 + bnq);
        As[0][akq + 0][ar] = av.x;
        As[0][akq + 1][ar] = av.y;
        As[0][akq + 2][ar] = av.z;
        As[0][akq + 3][ar] = av.w;
        *(float4*)&Bs[0][bkk][bnq] = bv;
    }
    __syncthreads();

    int buf = 0;
    for (int k0 = 0; k0 < 512; k0 += 8) {
        float4 av, bv;
        const bool more = (k0 + 8 < 512);
        if (more) {
            av = *(const float4*)(Arow + k0 + 8 + akq);
            bv = *(const float4*)(Bmat + (size_t)(k0 + 8 + bkk) * 512 + c0 + bnq);
        }

        #pragma unroll
        for (int k = 0; k < 8; ++k) {
            ulonglong2 a01 = *(const ulonglong2*)&As[buf][k][ty * 8];
            ulonglong2 a23 = *(const ulonglong2*)&As[buf][k][ty * 8 + 4];
            float4 bA = *(const float4*)&Bs[buf][k][tx * 8];
            float4 bB = *(const float4*)&Bs[buf][k][tx * 8 + 4];
            ull bd[8];
            bd[0] = pack2(bA.x); bd[1] = pack2(bA.y);
            bd[2] = pack2(bA.z); bd[3] = pack2(bA.w);
            bd[4] = pack2(bB.x); bd[5] = pack2(bB.y);
            bd[6] = pack2(bB.z); bd[7] = pack2(bB.w);
            #pragma unroll
            for (int j = 0; j < 8; ++j) {
                acc[0][j] = ffma2(a01.x, bd[j], acc[0][j]);
                acc[1][j] = ffma2(a01.y, bd[j], acc[1][j]);
                acc[2][j] = ffma2(a23.x, bd[j], acc[2][j]);
                acc[3][j] = ffma2(a23.y, bd[j], acc[3][j]);
            }
        }

        if (more) {
            int nb = buf ^ 1;
            As[nb][akq + 0][ar] = av.x;
            As[nb][akq + 1][ar] = av.y;
            As[nb][akq + 2][ar] = av.z;
            As[nb][akq + 3][ar] = av.w;
            *(float4*)&Bs[nb][bkk][bnq] = bv;
            __syncthreads();
            buf = nb;
        }
    }

    const int cg = c0 + tx * 8;
    float4 bl = *(const float4*)(bias + cg);
    float4 bh = *(const float4*)(bias + cg + 4);
    #pragma unroll
    for (int mp = 0; mp < 4; ++mp) {
        float2 v[8];
        #pragma unroll
        for (int j = 0; j < 8; ++j) v[j] = unpack2(acc[mp][j]);
        #pragma unroll
        for (int p = 0; p < 2; ++p) {
            int m = m0 + ty * 8 + mp * 2 + p;
            int tt = m >> 5, bb2 = m & 31;
            float* dst = g_pre + ((size_t)dir * 512 + tt) * 16384 + (size_t)bb2 * 512 + cg;
            float4 o0, o1;
            o0.x = (p ? v[0].y : v[0].x) + bl.x;
            o0.y = (p ? v[1].y : v[1].x) + bl.y;
            o0.z = (p ? v[2].y : v[2].x) + bl.z;
            o0.w = (p ? v[3].y : v[3].x) + bl.w;
            o1.x = (p ? v[4].y : v[4].x) + bh.x;
            o1.y = (p ? v[5].y : v[5].x) + bh.y;
            o1.z = (p ? v[6].y : v[6].x) + bh.z;
            o1.w = (p ? v[7].y : v[7].x) + bh.w;
            *(float4*)dst = o0;
            *(float4*)(dst + 4) = o1;
        }
    }
}

// =================================================================================
// Kernel 2: persistent bidirectional recurrence (v4 — batch-group partitioning)
//   128 CTAs = 2 dirs x 4 batch-groups(8) x 16 col-slices(32), 512 threads.
//   Thread = (c in 0..31, ks in 0..15): Wh[ks*32..+31][c0+c] in 16 f32x2 regs,
//   computes partials for all 8 batches of its group.
//   Per step: stage 16KB h (8 rows x 512) in one shot, compute, 16-way reduce,
//   tanh, store; per-(dir,group) 16-CTA barrier.
// =================================================================================
__global__ __launch_bounds__(512) void recur_kernel(
    const float* __restrict__ Wf, const float* __restrict__ Wb)
{
    __shared__ float s_h[8 * 520];      // [8 batches][512+8]
    __shared__ float s_red[16 * 256];   // [ks][b*32+c]

    const int tid = threadIdx.x;
    const int bx  = blockIdx.x;
    const int dir = bx & 1;
    const int grp = (bx >> 1) & 3;          // batch group 0..3
    const int sl  = bx >> 3;                // col slice 0..15
    const int c0  = sl * 32;
    const int bgl = grp * 8;                // first global batch of group
    const float* W = dir ? Wb : Wf;

    const int c  = tid & 31;                // col within slice
    const int ks = tid >> 5;                // k-split 0..15 (k = ks*32..+31)

    // Wh column (c0+c), k in [ks*32, ks*32+32) -> 16 f32x2 regs
    ull wreg[8][2];
    #pragma unroll
    for (int j = 0; j < 8; ++j) {
        int k = ks * 32 + j * 4;
        const float* wp = W + (size_t)(512 + k) * 512 + c0 + c;
        wreg[j][0] = packab(wp[0],    wp[512]);
        wreg[j][1] = packab(wp[1024], wp[1536]);
    }

    // staging map: 1024 float4s total, thread loads q=tid and q=tid+512
    const int sb0  = tid >> 7;              // 0..3
    const int sb1  = (tid + 512) >> 7;      // 4..7
    const int soff = (tid & 127) * 4;       // float offset in 512-row

    // reduce/store map (tid < 256): batch rb, col rc
    const int rb = tid >> 5;
    const int rc = tid & 31;

    unsigned int* bar = &g_bar8[dir * 4 + grp];

    for (int s = 0; s < 512; ++s) {
        const int t = dir ? (511 - s) : s;

        float pre = 0.f;
        if (tid < 256)
            pre = __ldcg(&g_pre[((size_t)dir * 512 + t) * 16384 +
                                (size_t)(bgl + rb) * 512 + c0 + rc]);

        float hval = 0.f;
        if (s == 0) {
            if (tid < 256) hval = tanhf(pre);
        } else {
            const int tp = dir ? (t + 1) : (t - 1);
            const float* hbase = g_hs + (size_t)tp * 32 * 1024 +
                                 (size_t)bgl * 1024 + dir * 512;

            // stage all 8 h rows (16KB) in one shot
            float4 v0 = __ldcg((const float4*)(hbase + sb0 * 1024 + soff));
            float4 v1 = __ldcg((const float4*)(hbase + sb1 * 1024 + soff));
            *(float4*)&s_h[sb0 * 520 + soff] = v0;
            *(float4*)&s_h[sb1 * 520 + soff] = v1;
            __syncthreads();

            // mat-vec partials: all smem reads are warp-broadcast (ks const/warp)
            ull acc[8];
            #pragma unroll
            for (int b = 0; b < 8; ++b) acc[b] = 0ull;
            #pragma unroll
            for (int b = 0; b < 8; ++b) {
                const ulonglong2* hp = (const ulonglong2*)&s_h[b * 520 + ks * 32];
                #pragma unroll
                for (int j = 0; j < 8; ++j) {
                    ulonglong2 h2 = hp[j];
                    acc[b] = ffma2(h2.x, wreg[j][0], acc[b]);
                    acc[b] = ffma2(h2.y, wreg[j][1], acc[b]);
                }
            }
            #pragma unroll
            for (int b = 0; b < 8; ++b) {
                float2 p = unpack2(acc[b]);
                s_red[ks * 256 + b * 32 + c] = p.x + p.y;
            }
            __syncthreads();

            if (tid < 256) {
                float sum = pre;
                #pragma unroll
                for (int k16 = 0; k16 < 16; ++k16) sum += s_red[k16 * 256 + tid];
                hval = tanhf(sum);
            }
        }

        if (tid < 256)
            __stcg(&g_hs[((size_t)t * 32 + bgl + rb) * 1024 +
                         dir * 512 + c0 + rc], hval);

        if (s < 511) {
            __syncthreads();   // CTA-HB: h stores before release; also guards s_h reuse
            if (tid == 0) {
                asm volatile("red.release.gpu.global.add.u32 [%0], 1;"
                             :: "l"(bar) : "memory");
                const unsigned target = (unsigned)(s + 1) * 16u;
                unsigned v;
                for (;;) {
                    asm volatile("ld.acquire.gpu.global.u32 %0, [%1];"
                                 : "=r"(v) : "l"(bar) : "memory");
                    if (v >= target) break;
                    __nanosleep(32);
                }
            }
            __syncthreads();
        }
    }
}

// =================================================================================
// Kernel 3: output GEMM (double-buffered smem)
// =================================================================================
__global__ __launch_bounds__(256) void out_gemm(
    const float* __restrict__ Wo, const float* __restrict__ bo,
    float* __restrict__ out)
{
    __shared__ float As[2][8][132];
    __shared__ float Bs[2][8][136];

    const int tid = threadIdx.x;
    const int m0 = blockIdx.y * 128;
    const int n0 = blockIdx.x * 128;

    const int ar  = tid >> 1;
    const int akq = (tid & 1) * 4;
    const float* Arow = g_hs + (size_t)(m0 + ar) * 1024;

    const int bkk = tid >> 5;
    const int bnq = (tid & 31) * 4;

    const int ty = tid >> 4;
    const int tx = tid & 15;

    ull acc[4][8];
    #pragma unroll
    for (int i = 0; i < 4; ++i)
        #pragma unroll
        for (int j = 0; j < 8; ++j) acc[i][j] = 0ull;

    {
        float4 av = *(const float4*)(Arow + akq);
        float4 bv = *(const float4*)(Wo + (size_t)bkk * 512 + n0 + bnq);
        As[0][akq + 0][ar] = av.x;
        As[0][akq + 1][ar] = av.y;
        As[0][akq + 2][ar] = av.z;
        As[0][akq + 3][ar] = av.w;
        *(float4*)&Bs[0][bkk][bnq] = bv;
    }
    __syncthreads();

    int buf = 0;
    for (int k0 = 0; k0 < 1024; k0 += 8) {
        float4 av, bv;
        const bool more = (k0 + 8 < 1024);
        if (more) {
            av = *(const float4*)(Arow + k0 + 8 + akq);
            bv = *(const float4*)(Wo + (size_t)(k0 + 8 + bkk) * 512 + n0 + bnq);
        }

        #pragma unroll
        for (int k = 0; k < 8; ++k) {
            ulonglong2 a01 = *(const ulonglong2*)&As[buf][k][ty * 8];
            ulonglong2 a23 = *(const ulonglong2*)&As[buf][k][ty * 8 + 4];
            float4 bA = *(const float4*)&Bs[buf][k][tx * 8];
            float4 bB = *(const float4*)&Bs[buf][k][tx * 8 + 4];
            ull bd[8];
            bd[0] = pack2(bA.x); bd[1] = pack2(bA.y);
            bd[2] = pack2(bA.z); bd[3] = pack2(bA.w);
            bd[4] = pack2(bB.x); bd[5] = pack2(bB.y);
            bd[6] = pack2(bB.z); bd[7] = pack2(bB.w);
            #pragma unroll
            for (int j = 0; j < 8; ++j) {
                acc[0][j] = ffma2(a01.x, bd[j], acc[0][j]);
                acc[1][j] = ffma2(a01.y, bd[j], acc[1][j]);
                acc[2][j] = ffma2(a23.x, bd[j], acc[2][j]);
                acc[3][j] = ffma2(a23.y, bd[j], acc[3][j]);
            }
        }

        if (more) {
            int nb = buf ^ 1;
            As[nb][akq + 0][ar] = av.x;
            As[nb][akq + 1][ar] = av.y;
            As[nb][akq + 2][ar] = av.z;
            As[nb][akq + 3][ar] = av.w;
            *(float4*)&Bs[nb][bkk][bnq] = bv;
            __syncthreads();
            buf = nb;
        }
    }

    const int og = n0 + tx * 8;
    float4 bl = *(const float4*)(bo + og);
    float4 bh = *(const float4*)(bo + og + 4);
    #pragma unroll
    for (int mp = 0; mp < 4; ++mp) {
        float2 v[8];
        #pragma unroll
        for (int j = 0; j < 8; ++j) v[j] = unpack2(acc[mp][j]);
        #pragma unroll
        for (int p = 0; p < 2; ++p) {
            int m = m0 + ty * 8 + mp * 2 + p;
            int tt = m >> 5, bb2 = m & 31;
            float* dst = out + ((size_t)bb2 * 512 + tt) * 512 + og;
            float4 o0, o1;
            o0.x = (p ? v[0].y : v[0].x) + bl.x;
            o0.y = (p ? v[1].y : v[1].x) + bl.y;
            o0.z = (p ? v[2].y : v[2].x) + bl.z;
            o0.w = (p ? v[3].y : v[3].x) + bl.w;
            o1.x = (p ? v[4].y : v[4].x) + bh.x;
            o1.y = (p ? v[5].y : v[5].x) + bh.y;
            o1.z = (p ? v[6].y : v[6].x) + bh.z;
            o1.w = (p ? v[7].y : v[7].x) + bh.w;
            *(float4*)dst = o0;
            *(float4*)(dst + 4) = o1;
        }
    }
}

// =================================================================================
extern "C" void kernel_launch(void* const* d_in, const int* in_sizes, int n_in,
                              void* d_out, int out_size)
{
    const float* X  = (const float*)d_in[0];
    const float* Wf = (const float*)d_in[1];
    const float* bf = (const float*)d_in[2];
    const float* Wb = (const float*)d_in[3];
    const float* bb = (const float*)d_in[4];
    const float* Wo = (const float*)d_in[5];
    const float* bo = (const float*)d_in[6];
    float* out = (float*)d_out;

    pre_gemm<<<dim3(8, 128), 256>>>(X, Wf, bf, Wb, bb);
    recur_kernel<<<128, 512>>>(Wf, Wb);
    out_gemm<<<dim3(4, 128), 256>>>(Wo, bo, out);
}